// round 6
// baseline (speedup 1.0000x reference)
#include <cuda_runtime.h>

// out[b,t,w,c] = x[b, t+w-9, c], zero-padded in t.  B=32, T=4096, W=19, C=30.
// Identity: out row (b,t) [570 floats] == contiguous x slice starting at
// flat element (b*4096 + t - 9)*30, with pad rows zeroed.
//
// Block = (b, tile of TT=64 t-rows). Stage (TT+18)*30 = 2460 floats of x into
// smem (pad pre-zeroed), then emit TT*570 = 36480 floats as float2 stores.
// float2 granularity => LDS.64 with 8B lane stride = conflict-free smem reads.
// 320 threads * 57 iterations = 18240 float2 exactly -> no bounds checks.
// 320 threads / 32 regs -> 6 CTAs per SM for stage/emit interleave.

#define T_DIM   4096
#define C_DIM   30
#define ROW     570             // W*C
#define PAD     9
#define TT      64              // t-rows per block
#define SROWS   (TT + 2*PAD)    // 82
#define SFLOATS (SROWS * C_DIM) // 2460
#define THREADS 320
#define ITERS   57              // TT*ROW/2 / THREADS = 18240/320

__device__ __forceinline__ void stg_cs_v2(float2* p, float2 v) {
    asm volatile("st.global.cs.v2.f32 [%0], {%1,%2};"
                 :: "l"(p), "f"(v.x), "f"(v.y) : "memory");
}

__global__ __launch_bounds__(THREADS)
void overlap_window_smem_kernel(const float* __restrict__ x,
                                float2* __restrict__ out2) {
    __shared__ float s[SFLOATS];

    const int tile = blockIdx.x;            // 0 .. 2047
    const int tpb  = T_DIM / TT;            // 64 tiles per batch
    const int b    = tile / tpb;
    const int t0   = (tile - b * tpb) * TT;
    const int tid  = threadIdx.x;

    // ---- stage x[(b*4096 + t0 - 9)*30 ... +2460) into smem, zeroing pad ----
    const int lo = (t0 == 0) ? (PAD * C_DIM) : 0;
    const int hi_raw = (T_DIM - t0 + PAD) * C_DIM;
    const int hi = hi_raw < SFLOATS ? hi_raw : SFLOATS;
    const int gbase = (b * T_DIM + t0 - PAD) * C_DIM;  // even
    const float2* __restrict__ x2 = (const float2*)x;
    float2* __restrict__ s2 = (float2*)s;

    #pragma unroll
    for (int k = 0; k < (SFLOATS / 2 + THREADS - 1) / THREADS; k++) {
        int idx2 = tid + k * THREADS;
        if (idx2 < SFLOATS / 2) {
            int i = idx2 * 2;
            float2 v = make_float2(0.0f, 0.0f);
            if (i >= lo && i < hi) {
                v = __ldg(&x2[(gbase >> 1) + idx2]);
            }
            s2[idx2] = v;
        }
    }
    __syncthreads();

    // ---- emit 18240 float2s; float2 index q = tid + k*320, element e = 2q ----
    // output row r = e/570, rem = e - 570r (even); smem source = r*30 + rem.
    // e advances by 640 per iter: rem += 70 (mod 570), r += 1; or rem += 640.
    float2* __restrict__ out_tile = out2 + ((size_t)(b * T_DIM + t0) * ROW) / 2;

    int e   = tid * 2;                  // 0..638
    int r   = (e >= ROW) ? 1 : 0;
    int rem = e - r * ROW;

    #pragma unroll
    for (int k = 0; k < ITERS; k++) {
        int src = r * C_DIM + rem;      // even -> 8B aligned
        float2 v = *(const float2*)&s[src];
        stg_cs_v2(&out_tile[tid + k * THREADS], v);

        // advance e += 640: either stays in row (rem+640 < 570 impossible since
        // 640 > 570? no: 640 - 570 = 70) -> r += 1, rem += 70, unless that
        // pushes past a second boundary.
        rem += 640 - ROW;               // += 70
        r   += 1;
        if (rem >= ROW) { rem -= ROW; r += 1; }
    }
}

extern "C" void kernel_launch(void* const* d_in, const int* in_sizes, int n_in,
                              void* d_out, int out_size) {
    const float* x = (const float*)d_in[0];
    float2* out2 = (float2*)d_out;
    const int blocks = 32 * (T_DIM / TT);   // 2048
    overlap_window_smem_kernel<<<blocks, THREADS>>>(x, out2);
}